// round 14
// baseline (speedup 1.0000x reference)
#include <cuda_runtime.h>
#include <cuda_bf16.h>
#include <math_constants.h>

#define NN 50000                 // nodes
#define NE 800000                // raw edges
#define NT (NE + NN)             // edges + self loops
#define NEG_SLOPE 0.2f
#define NB_SCAN ((NN + 1023) / 1024)   // 49 scan blocks
#define XPAD 132                 // padded shared row stride (floats), 16B aligned
#define NSPLIT 25024             // node split for agg1/gemm2 pipelining (32-aligned)

// ---------------- scratch ----------------
__device__ float g_h1[NN * 128];
__device__ float g_ssrc1[NN * 4];
__device__ float g_sdst1[NN * 4];
__device__ float g_out1[NN * 128];
__device__ float g_h2[NN * 64];
__device__ float g_ssrc2[NN];
__device__ float g_sdst2[NN];
__device__ int   g_cnt[NN];
__device__ int   g_rowptr[NN + 1];
__device__ int   g_cursor[NN];
__device__ int   g_csr_src[NT];
__device__ int   g_bsum[64];
__device__ int   g_boff[64];
__device__ int   g_is64;

// ---------------- helpers ----------------
__device__ __forceinline__ float lrelu(float v) { return v > 0.f ? v : NEG_SLOPE * v; }

__device__ __forceinline__ int edge_idx(const void* ei, int row, int e) {
    if (g_is64) return (int)((const long long*)ei)[(size_t)row * NE + e];
    else        return ((const int*)ei)[(size_t)row * NE + e];
}

// packed f32x2 helpers (Blackwell FFMA2 — only via PTX)
__device__ __forceinline__ unsigned long long pack2(float f) {
    unsigned long long r;
    asm("mov.b64 %0, {%1, %1};" : "=l"(r) : "f"(f));
    return r;
}
__device__ __forceinline__ unsigned long long fma2(unsigned long long a,
                                                   unsigned long long b,
                                                   unsigned long long c) {
    unsigned long long d;
    asm("fma.rn.f32x2 %0, %1, %2, %3;" : "=l"(d) : "l"(a), "l"(b), "l"(c));
    return d;
}
__device__ __forceinline__ void unpack2(unsigned long long v, float& lo, float& hi) {
    asm("mov.b64 {%0, %1}, %2;" : "=f"(lo), "=f"(hi) : "l"(v));
}

// ---------------- dtype detection ----------------
__global__ void detect_dtype(const unsigned int* __restrict__ ei_words) {
    __shared__ int any_nonzero;
    if (threadIdx.x == 0) any_nonzero = 0;
    __syncthreads();
    unsigned int w = ei_words[2 * threadIdx.x + 1];
    if (w != 0u) atomicOr(&any_nonzero, 1);
    __syncthreads();
    if (threadIdx.x == 0) g_is64 = any_nonzero ? 0 : 1;
}

// ---------------- CSR build (self-loops placed analytically) ----------------
__global__ void init_cnt() {
    int i = blockIdx.x * blockDim.x + threadIdx.x;
    if (i < NN) g_cnt[i] = 1;          // self-loop pre-counted
}

__global__ void hist_kernel(const void* __restrict__ ei) {
    int e = blockIdx.x * blockDim.x + threadIdx.x;
    if (e >= NE) return;
    atomicAdd(&g_cnt[edge_idx(ei, 1, e)], 1);
}

__global__ void scan1_kernel() {
    __shared__ int wsum[32];
    int t = threadIdx.x;
    int idx = blockIdx.x * 1024 + t;
    int v = (idx < NN) ? g_cnt[idx] : 0;
    int incl = v;
#pragma unroll
    for (int o = 1; o < 32; o <<= 1) {
        int nbr = __shfl_up_sync(0xffffffff, incl, o);
        if ((t & 31) >= o) incl += nbr;
    }
    if ((t & 31) == 31) wsum[t >> 5] = incl;
    __syncthreads();
    if (t < 32) {
        int ws = wsum[t];
        int wincl = ws;
#pragma unroll
        for (int o = 1; o < 32; o <<= 1) {
            int nbr = __shfl_up_sync(0xffffffff, wincl, o);
            if (t >= o) wincl += nbr;
        }
        wsum[t] = wincl - ws;
    }
    __syncthreads();
    int excl = incl - v + wsum[t >> 5];
    if (idx < NN) g_rowptr[idx] = excl;
    if (t == 1023) g_bsum[blockIdx.x] = excl + v;
}

__global__ void scan2_kernel() {
    __shared__ int s[64];
    int t = threadIdx.x;
    int v = (t < NB_SCAN) ? g_bsum[t] : 0;
    s[t] = v;
    __syncthreads();
#pragma unroll
    for (int o = 1; o < 64; o <<= 1) {
        int tmp = (t >= o) ? s[t - o] : 0;
        __syncthreads();
        s[t] += tmp;
        __syncthreads();
    }
    g_boff[t] = s[t] - v;
}

__global__ void scan3_kernel() {
    int idx = blockIdx.x * blockDim.x + threadIdx.x;
    if (idx == 0) g_rowptr[NN] = NT;
    if (idx >= NN) return;
    int r = g_rowptr[idx] + g_boff[idx >> 10];
    g_rowptr[idx] = r;
    g_csr_src[r] = idx;      // self-loop at slot 0 of the segment
    g_cursor[idx] = r + 1;
}

__global__ void scatter_kernel(const void* __restrict__ ei) {
    int e = blockIdx.x * blockDim.x + threadIdx.x;
    if (e >= NE) return;
    int s = edge_idx(ei, 0, e);
    int d = edge_idx(ei, 1, e);
    int pos = atomicAdd(&g_cursor[d], 1);
    g_csr_src[pos] = s;
}

// ---------------- layer1 GEMM: 32-node tile; warp = 4 nodes, lane = 4 cols ----------------
__global__ void __launch_bounds__(256, 3) gemm1_kernel(const float* __restrict__ x,
                             const float* __restrict__ W,
                             const float* __restrict__ a_src,
                             const float* __restrict__ a_dst) {
    __shared__ float xs[32][XPAD];
    int t = threadIdx.x;
    int tx = t & 31, ty = t >> 5;
    int nbase = blockIdx.x * 32;

    for (int i = t; i < 32 * 32; i += 256) {
        int n = i >> 5, kc = i & 31;
        int node = nbase + n;
        float4 v = (node < NN) ? ((const float4*)(x + (size_t)node * 128))[kc]
                               : make_float4(0.f, 0.f, 0.f, 0.f);
        *(float4*)&xs[n][kc * 4] = v;
    }
    __syncthreads();

    unsigned long long acc[4][2] = {};   // [node j][pair p] -> cols 4tx+2p, +1
    const ulonglong2* Wp = (const ulonglong2*)W;   // 4 floats; row k col c -> k*32 + c/4
#pragma unroll 2
    for (int k4 = 0; k4 < 128; k4 += 4) {
        float4 xv[4];
#pragma unroll
        for (int j = 0; j < 4; j++) xv[j] = *(const float4*)&xs[ty * 4 + j][k4];
#pragma unroll
        for (int kk = 0; kk < 4; kk++) {
            ulonglong2 wv = Wp[(k4 + kk) * 32 + tx];   // cols 4tx..4tx+3
#pragma unroll
            for (int j = 0; j < 4; j++) {
                float xf = (kk == 0) ? xv[j].x : (kk == 1) ? xv[j].y
                         : (kk == 2) ? xv[j].z : xv[j].w;
                unsigned long long xp = pack2(xf);
                acc[j][0] = fma2(xp, wv.x, acc[j][0]);
                acc[j][1] = fma2(xp, wv.y, acc[j][1]);
            }
        }
    }

    int h = tx >> 3;                      // head owning cols 4tx..
    float4 as = *(const float4*)(a_src + 4 * tx);
    float4 ad = *(const float4*)(a_dst + 4 * tx);

#pragma unroll
    for (int j = 0; j < 4; j++) {
        int node = nbase + ty * 4 + j;
        float f0, f1, f2, f3;
        unpack2(acc[j][0], f0, f1);
        unpack2(acc[j][1], f2, f3);
        if (node < NN) {
            *(ulonglong2*)(g_h1 + (size_t)node * 128 + 4 * tx) =
                make_ulonglong2(acc[j][0], acc[j][1]);
        }
        float ps = f0 * as.x + f1 * as.y + f2 * as.z + f3 * as.w;
        float pd = f0 * ad.x + f1 * ad.y + f2 * ad.z + f3 * ad.w;
        ps += __shfl_xor_sync(0xffffffff, ps, 1);
        ps += __shfl_xor_sync(0xffffffff, ps, 2);
        ps += __shfl_xor_sync(0xffffffff, ps, 4);
        pd += __shfl_xor_sync(0xffffffff, pd, 1);
        pd += __shfl_xor_sync(0xffffffff, pd, 2);
        pd += __shfl_xor_sync(0xffffffff, pd, 4);
        if ((tx & 7) == 0 && node < NN) {
            g_ssrc1[node * 4 + h] = ps;
            g_sdst1[node * 4 + h] = pd;
        }
    }
}

// ---------------- layer1 fused softmax + aggregation (warp per node), node range ----------
__global__ void agg1_kernel(const float* __restrict__ bias, int dbase, int dend) {
    __shared__ int   sh_s[8][32];
    __shared__ float sh_p[8][4][32];
    int w = threadIdx.x >> 5;
    int l = threadIdx.x & 31;
    int d = dbase + blockIdx.x * 8 + w;
    if (d >= dend) return;
    int start = g_rowptr[d];
    int end   = g_rowptr[d + 1];
    float4 sd = *(const float4*)(g_sdst1 + d * 4);
    int h = l >> 3;

    unsigned long long acc01 = 0ull, acc23 = 0ull;
    float4 den = make_float4(0.f, 0.f, 0.f, 0.f);
    for (int base = start; base < end; base += 32) {
        int i = base + l;
        int s_l = 0;
        float4 p_l = make_float4(0.f, 0.f, 0.f, 0.f);
        if (i < end) {
            s_l = g_csr_src[i];
            float4 ss = *(const float4*)(g_ssrc1 + s_l * 4);
            p_l.x = __expf(lrelu(ss.x + sd.x));
            p_l.y = __expf(lrelu(ss.y + sd.y));
            p_l.z = __expf(lrelu(ss.z + sd.z));
            p_l.w = __expf(lrelu(ss.w + sd.w));
            den.x += p_l.x; den.y += p_l.y; den.z += p_l.z; den.w += p_l.w;
        }
        sh_s[w][l] = s_l;
        sh_p[w][0][l] = p_l.x;
        sh_p[w][1][l] = p_l.y;
        sh_p[w][2][l] = p_l.z;
        sh_p[w][3][l] = p_l.w;
        __syncwarp();
        int cnt = min(32, end - base);
        for (int j = 0; j < cnt; j++) {
            int   s  = sh_s[w][j];
            float ph = sh_p[w][h][j];
            ulonglong2 hv = *(const ulonglong2*)(g_h1 + (size_t)s * 128 + 4 * l);
            unsigned long long p2 = pack2(ph);
            acc01 = fma2(p2, hv.x, acc01);
            acc23 = fma2(p2, hv.y, acc23);
        }
        __syncwarp();
    }
#pragma unroll
    for (int o = 16; o; o >>= 1) {
        den.x += __shfl_xor_sync(0xffffffff, den.x, o);
        den.y += __shfl_xor_sync(0xffffffff, den.y, o);
        den.z += __shfl_xor_sync(0xffffffff, den.z, o);
        den.w += __shfl_xor_sync(0xffffffff, den.w, o);
    }
    float denh = (h == 0) ? den.x : (h == 1) ? den.y : (h == 2) ? den.z : den.w;

    float a0, a1, a2, a3;
    unpack2(acc01, a0, a1);
    unpack2(acc23, a2, a3);
    float4 bv = *(const float4*)(bias + 4 * l);
    float4 o;
    o.x = fmaxf(a0 / denh + bv.x, 0.f);
    o.y = fmaxf(a1 / denh + bv.y, 0.f);
    o.z = fmaxf(a2 / denh + bv.z, 0.f);
    o.w = fmaxf(a3 / denh + bv.w, 0.f);
    ((float4*)(g_out1 + (size_t)d * 128))[l] = o;
}

// ---------------- layer2 GEMM: 32-node tile (offset), warp = 4 nodes, lane = 2 cols --------
__global__ void __launch_bounds__(256, 3) gemm2_kernel(const float* __restrict__ W,
                             const float* __restrict__ a_src,
                             const float* __restrict__ a_dst,
                             int nbase0) {
    __shared__ float xs[32][XPAD];
    int t = threadIdx.x;
    int tx = t & 31, ty = t >> 5;
    int nbase = nbase0 + blockIdx.x * 32;

    for (int i = t; i < 32 * 32; i += 256) {
        int n = i >> 5, kc = i & 31;
        int node = nbase + n;
        float4 v = (node < NN) ? ((const float4*)(g_out1 + (size_t)node * 128))[kc]
                               : make_float4(0.f, 0.f, 0.f, 0.f);
        *(float4*)&xs[n][kc * 4] = v;
    }
    __syncthreads();

    unsigned long long acc[4] = {};   // node j -> cols 2tx, 2tx+1
    const unsigned long long* Wp = (const unsigned long long*)W;   // row k col c -> k*32 + c/2
#pragma unroll 2
    for (int k4 = 0; k4 < 128; k4 += 4) {
        float4 xv[4];
#pragma unroll
        for (int j = 0; j < 4; j++) xv[j] = *(const float4*)&xs[ty * 4 + j][k4];
#pragma unroll
        for (int kk = 0; kk < 4; kk++) {
            unsigned long long wv = Wp[(k4 + kk) * 32 + tx];   // cols 2tx, 2tx+1
#pragma unroll
            for (int j = 0; j < 4; j++) {
                float xf = (kk == 0) ? xv[j].x : (kk == 1) ? xv[j].y
                         : (kk == 2) ? xv[j].z : xv[j].w;
                acc[j] = fma2(pack2(xf), wv, acc[j]);
            }
        }
    }

    float2 as = *(const float2*)(a_src + 2 * tx);
    float2 ad = *(const float2*)(a_dst + 2 * tx);
#pragma unroll
    for (int j = 0; j < 4; j++) {
        int node = nbase + ty * 4 + j;
        float f0, f1;
        unpack2(acc[j], f0, f1);
        if (node < NN) {
            *(unsigned long long*)(g_h2 + (size_t)node * 64 + 2 * tx) = acc[j];
        }
        float ps = f0 * as.x + f1 * as.y;
        float pd = f0 * ad.x + f1 * ad.y;
#pragma unroll
        for (int o = 1; o < 32; o <<= 1) {
            ps += __shfl_xor_sync(0xffffffff, ps, o);
            pd += __shfl_xor_sync(0xffffffff, pd, o);
        }
        if (tx == 0 && node < NN) {
            g_ssrc2[node] = ps;
            g_sdst2[node] = pd;
        }
    }
}

// ---------------- layer2 fused softmax + aggregation -> output, NO max pass ----------------
__global__ void agg2_kernel(const float* __restrict__ bias, float* __restrict__ out) {
    __shared__ int   sh_s[8][32];
    __shared__ float sh_p[8][32];
    int w = threadIdx.x >> 5;
    int l = threadIdx.x & 31;
    int d = blockIdx.x * 8 + w;
    if (d >= NN) return;
    int start = g_rowptr[d];
    int end   = g_rowptr[d + 1];
    float sdv = g_sdst2[d];

    unsigned long long acc = 0ull;
    float den = 0.f;
    for (int base = start; base < end; base += 32) {
        int i = base + l;
        int s_l = 0;
        float p_l = 0.f;
        if (i < end) {
            s_l = g_csr_src[i];
            p_l = __expf(lrelu(g_ssrc2[s_l] + sdv));
            den += p_l;
        }
        sh_s[w][l] = s_l;
        sh_p[w][l] = p_l;
        __syncwarp();
        int cnt = min(32, end - base);
        for (int j = 0; j < cnt; j++) {
            int   s = sh_s[w][j];
            float p = sh_p[w][j];
            unsigned long long hv = *(const unsigned long long*)(g_h2 + (size_t)s * 64 + 2 * l);
            acc = fma2(pack2(p), hv, acc);
        }
        __syncwarp();
    }
#pragma unroll
    for (int o = 16; o; o >>= 1) den += __shfl_xor_sync(0xffffffff, den, o);

    float a0, a1;
    unpack2(acc, a0, a1);
    float2 bv = *(const float2*)(bias + 2 * l);
    float2 o2;
    o2.x = a0 / den + bv.x;
    o2.y = a1 / den + bv.y;
    *(float2*)(out + (size_t)d * 64 + 2 * l) = o2;
}

// ---------------- launch: two-stream pipeline ----------------
extern "C" void kernel_launch(void* const* d_in, const int* in_sizes, int n_in,
                              void* d_out, int out_size) {
    const float* x     = (const float*)d_in[0];
    const void*  ei    = d_in[1];
    const float* W1    = (const float*)d_in[2];
    const float* asrc1 = (const float*)d_in[3];
    const float* adst1 = (const float*)d_in[4];
    const float* b1    = (const float*)d_in[5];
    const float* W2    = (const float*)d_in[6];
    const float* asrc2 = (const float*)d_in[7];
    const float* adst2 = (const float*)d_in[8];
    const float* b2    = (const float*)d_in[9];
    float* out = (float*)d_out;

    const int T = 256;
    const int NBG = (NN + 31) / 32;
    const int NBG2_LO = NSPLIT / 32;                       // 782
    const int NBG2_HI = (NN - NSPLIT + 31) / 32;           // 781
    const int NAGG_LO = NSPLIT / 8;                        // 3128
    const int NAGG_HI = (NN - NSPLIT + 7) / 8;             // 3122

    cudaStream_t s2;
    cudaStreamCreateWithFlags(&s2, cudaStreamNonBlocking);
    cudaEvent_t ev_fork, ev_csr, ev_g1, ev_hi;
    cudaEventCreateWithFlags(&ev_fork, cudaEventDisableTiming);
    cudaEventCreateWithFlags(&ev_csr, cudaEventDisableTiming);
    cudaEventCreateWithFlags(&ev_g1, cudaEventDisableTiming);
    cudaEventCreateWithFlags(&ev_hi, cudaEventDisableTiming);

    // fork s2 off the main stream head (captures cleanly)
    cudaEventRecord(ev_fork, 0);
    cudaStreamWaitEvent(s2, ev_fork, 0);

    // side stream: dtype detect + full CSR build
    detect_dtype<<<1, 128, 0, s2>>>((const unsigned int*)ei);
    init_cnt<<<(NN + T - 1) / T, T, 0, s2>>>();
    hist_kernel<<<(NE + T - 1) / T, T, 0, s2>>>(ei);
    scan1_kernel<<<NB_SCAN, 1024, 0, s2>>>();
    scan2_kernel<<<1, 64, 0, s2>>>();
    scan3_kernel<<<(NN + T - 1) / T, T, 0, s2>>>();
    scatter_kernel<<<(NE + T - 1) / T, T, 0, s2>>>(ei);
    cudaEventRecord(ev_csr, s2);

    // main stream: gemm1 concurrent with CSR build
    gemm1_kernel<<<NBG, 256>>>(x, W1, asrc1, adst1);
    cudaEventRecord(ev_g1, 0);

    // main: agg1 low half (needs CSR + gemm1)
    cudaStreamWaitEvent(0, ev_csr, 0);
    agg1_kernel<<<NAGG_LO, 256>>>(b1, 0, NSPLIT);

    // side: agg1 high half (CSR in program order; wait for gemm1)
    cudaStreamWaitEvent(s2, ev_g1, 0);
    agg1_kernel<<<NAGG_HI, 256, 0, s2>>>(b1, NSPLIT, NN);
    cudaEventRecord(ev_hi, s2);

    // main: gemm2 low half overlaps agg1 high half
    gemm2_kernel<<<NBG2_LO, 256>>>(W2, asrc2, adst2, 0);
    cudaStreamWaitEvent(0, ev_hi, 0);
    gemm2_kernel<<<NBG2_HI, 256>>>(W2, asrc2, adst2, NSPLIT);

    agg2_kernel<<<(NN + 7) / 8, 256>>>(b2, out);

    cudaEventDestroy(ev_fork);
    cudaEventDestroy(ev_csr);
    cudaEventDestroy(ev_g1);
    cudaEventDestroy(ev_hi);
    cudaStreamDestroy(s2);
}

// round 15
// speedup vs baseline: 1.0410x; 1.0410x over previous
#include <cuda_runtime.h>
#include <cuda_bf16.h>
#include <math_constants.h>

#define NN 50000                 // nodes
#define NE 800000                // raw edges
#define NT (NE + NN)             // edges + self loops
#define NEG_SLOPE 0.2f
#define NB_SCAN ((NN + 1023) / 1024)   // 49 scan blocks
#define XPAD 132                 // padded shared row stride (floats), 16B aligned
#define SPLIT1 33344             // agg1/gemm2 pipeline split (mult of 32)

// ---------------- scratch ----------------
__device__ float g_h1[NN * 128];
__device__ float g_ssrc1[NN * 4];
__device__ float g_sdst1[NN * 4];
__device__ float g_out1[NN * 128];
__device__ float g_h2[NN * 64];
__device__ float g_ssrc2[NN];
__device__ float g_sdst2[NN];
__device__ int   g_cnt[NN];
__device__ int   g_rowptr[NN + 1];
__device__ int   g_cursor[NN];
__device__ int   g_csr_src[NT];
__device__ int   g_bsum[64];
__device__ int   g_boff[64];
__device__ int   g_is64;

// ---------------- helpers ----------------
__device__ __forceinline__ float lrelu(float v) { return v > 0.f ? v : NEG_SLOPE * v; }

__device__ __forceinline__ int edge_idx(const void* ei, int row, int e) {
    if (g_is64) return (int)((const long long*)ei)[(size_t)row * NE + e];
    else        return ((const int*)ei)[(size_t)row * NE + e];
}

// packed f32x2 helpers (Blackwell FFMA2 — only via PTX)
__device__ __forceinline__ unsigned long long pack2(float f) {
    unsigned long long r;
    asm("mov.b64 %0, {%1, %1};" : "=l"(r) : "f"(f));
    return r;
}
__device__ __forceinline__ unsigned long long fma2(unsigned long long a,
                                                   unsigned long long b,
                                                   unsigned long long c) {
    unsigned long long d;
    asm("fma.rn.f32x2 %0, %1, %2, %3;" : "=l"(d) : "l"(a), "l"(b), "l"(c));
    return d;
}
__device__ __forceinline__ void unpack2(unsigned long long v, float& lo, float& hi) {
    asm("mov.b64 {%0, %1}, %2;" : "=f"(lo), "=f"(hi) : "l"(v));
}

// ---------------- dtype detection ----------------
__global__ void detect_dtype(const unsigned int* __restrict__ ei_words) {
    __shared__ int any_nonzero;
    if (threadIdx.x == 0) any_nonzero = 0;
    __syncthreads();
    unsigned int w = ei_words[2 * threadIdx.x + 1];
    if (w != 0u) atomicOr(&any_nonzero, 1);
    __syncthreads();
    if (threadIdx.x == 0) g_is64 = any_nonzero ? 0 : 1;
}

// ---------------- CSR build (self-loops placed analytically) ----------------
__global__ void init_cnt() {
    int i = blockIdx.x * blockDim.x + threadIdx.x;
    if (i < NN) g_cnt[i] = 1;          // self-loop pre-counted
}

__global__ void hist_kernel(const void* __restrict__ ei) {
    int e = blockIdx.x * blockDim.x + threadIdx.x;
    if (e >= NE) return;
    atomicAdd(&g_cnt[edge_idx(ei, 1, e)], 1);
}

__global__ void scan1_kernel() {
    __shared__ int wsum[32];
    int t = threadIdx.x;
    int idx = blockIdx.x * 1024 + t;
    int v = (idx < NN) ? g_cnt[idx] : 0;
    int incl = v;
#pragma unroll
    for (int o = 1; o < 32; o <<= 1) {
        int nbr = __shfl_up_sync(0xffffffff, incl, o);
        if ((t & 31) >= o) incl += nbr;
    }
    if ((t & 31) == 31) wsum[t >> 5] = incl;
    __syncthreads();
    if (t < 32) {
        int ws = wsum[t];
        int wincl = ws;
#pragma unroll
        for (int o = 1; o < 32; o <<= 1) {
            int nbr = __shfl_up_sync(0xffffffff, wincl, o);
            if (t >= o) wincl += nbr;
        }
        wsum[t] = wincl - ws;
    }
    __syncthreads();
    int excl = incl - v + wsum[t >> 5];
    if (idx < NN) g_rowptr[idx] = excl;
    if (t == 1023) g_bsum[blockIdx.x] = excl + v;
}

__global__ void scan2_kernel() {
    __shared__ int s[64];
    int t = threadIdx.x;
    int v = (t < NB_SCAN) ? g_bsum[t] : 0;
    s[t] = v;
    __syncthreads();
#pragma unroll
    for (int o = 1; o < 64; o <<= 1) {
        int tmp = (t >= o) ? s[t - o] : 0;
        __syncthreads();
        s[t] += tmp;
        __syncthreads();
    }
    g_boff[t] = s[t] - v;
}

__global__ void scan3_kernel() {
    int idx = blockIdx.x * blockDim.x + threadIdx.x;
    if (idx == 0) g_rowptr[NN] = NT;
    if (idx >= NN) return;
    int r = g_rowptr[idx] + g_boff[idx >> 10];
    g_rowptr[idx] = r;
    g_csr_src[r] = idx;      // self-loop at slot 0 of the segment
    g_cursor[idx] = r + 1;
}

__global__ void scatter_kernel(const void* __restrict__ ei) {
    int e = blockIdx.x * blockDim.x + threadIdx.x;
    if (e >= NE) return;
    int s = edge_idx(ei, 0, e);
    int d = edge_idx(ei, 1, e);
    int pos = atomicAdd(&g_cursor[d], 1);
    g_csr_src[pos] = s;
}

// ---------------- layer1 GEMM: 32-node tile; warp = 4 nodes, lane = 4 cols ----------------
__global__ void __launch_bounds__(256, 3) gemm1_kernel(const float* __restrict__ x,
                             const float* __restrict__ W,
                             const float* __restrict__ a_src,
                             const float* __restrict__ a_dst) {
    __shared__ float xs[32][XPAD];
    int t = threadIdx.x;
    int tx = t & 31, ty = t >> 5;
    int nbase = blockIdx.x * 32;

    for (int i = t; i < 32 * 32; i += 256) {
        int n = i >> 5, kc = i & 31;
        int node = nbase + n;
        float4 v = (node < NN) ? ((const float4*)(x + (size_t)node * 128))[kc]
                               : make_float4(0.f, 0.f, 0.f, 0.f);
        *(float4*)&xs[n][kc * 4] = v;
    }
    __syncthreads();

    unsigned long long acc[4][2] = {};   // [node j][pair p] -> cols 4tx+2p, +1
    const ulonglong2* Wp = (const ulonglong2*)W;   // 4 floats; row k col c -> k*32 + c/4
#pragma unroll 2
    for (int k4 = 0; k4 < 128; k4 += 4) {
        float4 xv[4];
#pragma unroll
        for (int j = 0; j < 4; j++) xv[j] = *(const float4*)&xs[ty * 4 + j][k4];
#pragma unroll
        for (int kk = 0; kk < 4; kk++) {
            ulonglong2 wv = Wp[(k4 + kk) * 32 + tx];   // cols 4tx..4tx+3
#pragma unroll
            for (int j = 0; j < 4; j++) {
                float xf = (kk == 0) ? xv[j].x : (kk == 1) ? xv[j].y
                         : (kk == 2) ? xv[j].z : xv[j].w;
                unsigned long long xp = pack2(xf);
                acc[j][0] = fma2(xp, wv.x, acc[j][0]);
                acc[j][1] = fma2(xp, wv.y, acc[j][1]);
            }
        }
    }

    int h = tx >> 3;                      // head owning cols 4tx..
    float4 as = *(const float4*)(a_src + 4 * tx);
    float4 ad = *(const float4*)(a_dst + 4 * tx);

#pragma unroll
    for (int j = 0; j < 4; j++) {
        int node = nbase + ty * 4 + j;
        float f0, f1, f2, f3;
        unpack2(acc[j][0], f0, f1);
        unpack2(acc[j][1], f2, f3);
        if (node < NN) {
            *(ulonglong2*)(g_h1 + (size_t)node * 128 + 4 * tx) =
                make_ulonglong2(acc[j][0], acc[j][1]);
        }
        float ps = f0 * as.x + f1 * as.y + f2 * as.z + f3 * as.w;
        float pd = f0 * ad.x + f1 * ad.y + f2 * ad.z + f3 * ad.w;
        ps += __shfl_xor_sync(0xffffffff, ps, 1);
        ps += __shfl_xor_sync(0xffffffff, ps, 2);
        ps += __shfl_xor_sync(0xffffffff, ps, 4);
        pd += __shfl_xor_sync(0xffffffff, pd, 1);
        pd += __shfl_xor_sync(0xffffffff, pd, 2);
        pd += __shfl_xor_sync(0xffffffff, pd, 4);
        if ((tx & 7) == 0 && node < NN) {
            g_ssrc1[node * 4 + h] = ps;
            g_sdst1[node * 4 + h] = pd;
        }
    }
}

// ---------------- layer1 fused softmax + aggregation (warp per node), node range ----------
__global__ void agg1_kernel(const float* __restrict__ bias, int dbase, int dend) {
    __shared__ int   sh_s[8][32];
    __shared__ float sh_p[8][4][32];
    int w = threadIdx.x >> 5;
    int l = threadIdx.x & 31;
    int d = dbase + blockIdx.x * 8 + w;
    if (d >= dend) return;
    int start = g_rowptr[d];
    int end   = g_rowptr[d + 1];
    float4 sd = *(const float4*)(g_sdst1 + d * 4);
    int h = l >> 3;

    unsigned long long acc01 = 0ull, acc23 = 0ull;
    float4 den = make_float4(0.f, 0.f, 0.f, 0.f);
    for (int base = start; base < end; base += 32) {
        int i = base + l;
        int s_l = 0;
        float4 p_l = make_float4(0.f, 0.f, 0.f, 0.f);
        if (i < end) {
            s_l = g_csr_src[i];
            float4 ss = *(const float4*)(g_ssrc1 + s_l * 4);
            p_l.x = __expf(lrelu(ss.x + sd.x));
            p_l.y = __expf(lrelu(ss.y + sd.y));
            p_l.z = __expf(lrelu(ss.z + sd.z));
            p_l.w = __expf(lrelu(ss.w + sd.w));
            den.x += p_l.x; den.y += p_l.y; den.z += p_l.z; den.w += p_l.w;
        }
        sh_s[w][l] = s_l;
        sh_p[w][0][l] = p_l.x;
        sh_p[w][1][l] = p_l.y;
        sh_p[w][2][l] = p_l.z;
        sh_p[w][3][l] = p_l.w;
        __syncwarp();
        int cnt = min(32, end - base);
        for (int j = 0; j < cnt; j++) {
            int   s  = sh_s[w][j];
            float ph = sh_p[w][h][j];
            ulonglong2 hv = *(const ulonglong2*)(g_h1 + (size_t)s * 128 + 4 * l);
            unsigned long long p2 = pack2(ph);
            acc01 = fma2(p2, hv.x, acc01);
            acc23 = fma2(p2, hv.y, acc23);
        }
        __syncwarp();
    }
#pragma unroll
    for (int o = 16; o; o >>= 1) {
        den.x += __shfl_xor_sync(0xffffffff, den.x, o);
        den.y += __shfl_xor_sync(0xffffffff, den.y, o);
        den.z += __shfl_xor_sync(0xffffffff, den.z, o);
        den.w += __shfl_xor_sync(0xffffffff, den.w, o);
    }
    float denh = (h == 0) ? den.x : (h == 1) ? den.y : (h == 2) ? den.z : den.w;

    float a0, a1, a2, a3;
    unpack2(acc01, a0, a1);
    unpack2(acc23, a2, a3);
    float4 bv = *(const float4*)(bias + 4 * l);
    float4 o;
    o.x = fmaxf(a0 / denh + bv.x, 0.f);
    o.y = fmaxf(a1 / denh + bv.y, 0.f);
    o.z = fmaxf(a2 / denh + bv.z, 0.f);
    o.w = fmaxf(a3 / denh + bv.w, 0.f);
    ((float4*)(g_out1 + (size_t)d * 128))[l] = o;
}

// ---------------- layer2 GEMM: 32-node tile (offset), warp = 4 nodes, lane = 2 cols --------
__global__ void __launch_bounds__(256, 3) gemm2_kernel(const float* __restrict__ W,
                             const float* __restrict__ a_src,
                             const float* __restrict__ a_dst,
                             int nbase0) {
    __shared__ float xs[32][XPAD];
    int t = threadIdx.x;
    int tx = t & 31, ty = t >> 5;
    int nbase = nbase0 + blockIdx.x * 32;

    for (int i = t; i < 32 * 32; i += 256) {
        int n = i >> 5, kc = i & 31;
        int node = nbase + n;
        float4 v = (node < NN) ? ((const float4*)(g_out1 + (size_t)node * 128))[kc]
                               : make_float4(0.f, 0.f, 0.f, 0.f);
        *(float4*)&xs[n][kc * 4] = v;
    }
    __syncthreads();

    unsigned long long acc[4] = {};   // node j -> cols 2tx, 2tx+1
    const unsigned long long* Wp = (const unsigned long long*)W;   // row k col c -> k*32 + c/2
#pragma unroll 2
    for (int k4 = 0; k4 < 128; k4 += 4) {
        float4 xv[4];
#pragma unroll
        for (int j = 0; j < 4; j++) xv[j] = *(const float4*)&xs[ty * 4 + j][k4];
#pragma unroll
        for (int kk = 0; kk < 4; kk++) {
            unsigned long long wv = Wp[(k4 + kk) * 32 + tx];   // cols 2tx, 2tx+1
#pragma unroll
            for (int j = 0; j < 4; j++) {
                float xf = (kk == 0) ? xv[j].x : (kk == 1) ? xv[j].y
                         : (kk == 2) ? xv[j].z : xv[j].w;
                acc[j] = fma2(pack2(xf), wv, acc[j]);
            }
        }
    }

    float2 as = *(const float2*)(a_src + 2 * tx);
    float2 ad = *(const float2*)(a_dst + 2 * tx);
#pragma unroll
    for (int j = 0; j < 4; j++) {
        int node = nbase + ty * 4 + j;
        float f0, f1;
        unpack2(acc[j], f0, f1);
        if (node < NN) {
            *(unsigned long long*)(g_h2 + (size_t)node * 64 + 2 * tx) = acc[j];
        }
        float ps = f0 * as.x + f1 * as.y;
        float pd = f0 * ad.x + f1 * ad.y;
#pragma unroll
        for (int o = 1; o < 32; o <<= 1) {
            ps += __shfl_xor_sync(0xffffffff, ps, o);
            pd += __shfl_xor_sync(0xffffffff, pd, o);
        }
        if (tx == 0 && node < NN) {
            g_ssrc2[node] = ps;
            g_sdst2[node] = pd;
        }
    }
}

// ---------------- layer2 fused softmax + aggregation -> output, NO max pass ----------------
__global__ void agg2_kernel(const float* __restrict__ bias, float* __restrict__ out) {
    __shared__ int   sh_s[8][32];
    __shared__ float sh_p[8][32];
    int w = threadIdx.x >> 5;
    int l = threadIdx.x & 31;
    int d = blockIdx.x * 8 + w;
    if (d >= NN) return;
    int start = g_rowptr[d];
    int end   = g_rowptr[d + 1];
    float sdv = g_sdst2[d];

    unsigned long long acc = 0ull;
    float den = 0.f;
    for (int base = start; base < end; base += 32) {
        int i = base + l;
        int s_l = 0;
        float p_l = 0.f;
        if (i < end) {
            s_l = g_csr_src[i];
            p_l = __expf(lrelu(g_ssrc2[s_l] + sdv));
            den += p_l;
        }
        sh_s[w][l] = s_l;
        sh_p[w][l] = p_l;
        __syncwarp();
        int cnt = min(32, end - base);
        for (int j = 0; j < cnt; j++) {
            int   s = sh_s[w][j];
            float p = sh_p[w][j];
            unsigned long long hv = *(const unsigned long long*)(g_h2 + (size_t)s * 64 + 2 * l);
            acc = fma2(pack2(p), hv, acc);
        }
        __syncwarp();
    }
#pragma unroll
    for (int o = 16; o; o >>= 1) den += __shfl_xor_sync(0xffffffff, den, o);

    float a0, a1;
    unpack2(acc, a0, a1);
    float2 bv = *(const float2*)(bias + 2 * l);
    float2 o2;
    o2.x = a0 / den + bv.x;
    o2.y = a1 / den + bv.y;
    *(float2*)(out + (size_t)d * 64 + 2 * l) = o2;
}

// ---------------- launch: R13 overlap + gemm2_lo under agg1_hi ----------------
extern "C" void kernel_launch(void* const* d_in, const int* in_sizes, int n_in,
                              void* d_out, int out_size) {
    const float* x     = (const float*)d_in[0];
    const void*  ei    = d_in[1];
    const float* W1    = (const float*)d_in[2];
    const float* asrc1 = (const float*)d_in[3];
    const float* adst1 = (const float*)d_in[4];
    const float* b1    = (const float*)d_in[5];
    const float* W2    = (const float*)d_in[6];
    const float* asrc2 = (const float*)d_in[7];
    const float* adst2 = (const float*)d_in[8];
    const float* b2    = (const float*)d_in[9];
    float* out = (float*)d_out;

    const int T = 256;
    const int NBG = (NN + 31) / 32;
    const int NAGG_LO = SPLIT1 / 8;
    const int NAGG_HI = (NN - SPLIT1 + 7) / 8;
    const int NBG2_LO = SPLIT1 / 32;
    const int NBG2_HI = (NN - SPLIT1 + 31) / 32;

    cudaStream_t s2;
    cudaStreamCreateWithFlags(&s2, cudaStreamNonBlocking);
    cudaEvent_t ev_fork, ev_csr, ev_a1lo, ev_g2lo;
    cudaEventCreateWithFlags(&ev_fork, cudaEventDisableTiming);
    cudaEventCreateWithFlags(&ev_csr, cudaEventDisableTiming);
    cudaEventCreateWithFlags(&ev_a1lo, cudaEventDisableTiming);
    cudaEventCreateWithFlags(&ev_g2lo, cudaEventDisableTiming);

    // fork s2 off the main stream head
    cudaEventRecord(ev_fork, 0);
    cudaStreamWaitEvent(s2, ev_fork, 0);

    // side stream: dtype detect + full CSR build (hidden under gemm1)
    detect_dtype<<<1, 128, 0, s2>>>((const unsigned int*)ei);
    init_cnt<<<(NN + T - 1) / T, T, 0, s2>>>();
    hist_kernel<<<(NE + T - 1) / T, T, 0, s2>>>(ei);
    scan1_kernel<<<NB_SCAN, 1024, 0, s2>>>();
    scan2_kernel<<<1, 64, 0, s2>>>();
    scan3_kernel<<<(NN + T - 1) / T, T, 0, s2>>>();
    scatter_kernel<<<(NE + T - 1) / T, T, 0, s2>>>(ei);
    cudaEventRecord(ev_csr, s2);

    // main stream: gemm1 concurrent with CSR build
    gemm1_kernel<<<NBG, 256>>>(x, W1, asrc1, adst1);
    cudaStreamWaitEvent(0, ev_csr, 0);

    // main: agg1 lo (2/3), then hi (1/3) — sequential, single stream (both L2-bound)
    agg1_kernel<<<NAGG_LO, 256>>>(b1, 0, SPLIT1);
    cudaEventRecord(ev_a1lo, 0);
    agg1_kernel<<<NAGG_HI, 256>>>(b1, SPLIT1, NN);

    // side: gemm2 lo overlaps agg1 hi (FMA-bound vs L2-bound — disjoint pipes)
    cudaStreamWaitEvent(s2, ev_a1lo, 0);
    gemm2_kernel<<<NBG2_LO, 256, 0, s2>>>(W2, asrc2, adst2, 0);
    cudaEventRecord(ev_g2lo, s2);

    // main: gemm2 hi (needs only agg1_hi, already ordered), then join for agg2
    gemm2_kernel<<<NBG2_HI, 256>>>(W2, asrc2, adst2, SPLIT1);
    cudaStreamWaitEvent(0, ev_g2lo, 0);

    agg2_kernel<<<(NN + 7) / 8, 256>>>(b2, out);

    cudaEventDestroy(ev_fork);
    cudaEventDestroy(ev_csr);
    cudaEventDestroy(ev_a1lo);
    cudaEventDestroy(ev_g2lo);
    cudaStreamDestroy(s2);
}